// round 2
// baseline (speedup 1.0000x reference)
#include <cuda_runtime.h>
#include <cstdint>
#include <cstddef>

static const int NA = 40000;
static const int NE = 150000;

// ---------------- device scratch (static, no allocation) ----------------
__device__ float d_qkvA0[40000 * 768];   // type0 dst qkv table [n][t][192]
__device__ float d_qkvA1[40000 * 768];   // type1 dst qkv table
__device__ float d_kv0[40000 * 512];     // type0 src kv table (B nodes, fused b_proj)
__device__ float d_kv1[40000 * 512];     // type1 src kv table (A nodes, fused b_proj)
__device__ float d_sum0[40000 * 256];
__device__ float d_sum1[40000 * 256];
__device__ float d_cnt0[40000];
__device__ float d_cnt1[40000];
__device__ float d_Wf[2 * 128 * 64];     // fused (Wqkv_kv @ Wb)
__device__ float d_bfv[2 * 128];         // fused bias

// ---------------- zero accumulators ----------------
__global__ void zero_kernel() {
    size_t tid = (size_t)blockIdx.x * blockDim.x + threadIdx.x;
    size_t stride = (size_t)gridDim.x * blockDim.x;
    for (size_t i = tid; i < (size_t)NA * 256; i += stride) { d_sum0[i] = 0.f; d_sum1[i] = 0.f; }
    for (size_t i = tid; i < (size_t)NA; i += stride) { d_cnt0[i] = 0.f; d_cnt1[i] = 0.f; }
}

// ---------------- fused weight: Wf[g][c'] = sum_c Wqkv[64+g][c] * Wb[c][c'] ----------------
__global__ void fuse_w_kernel(const float* __restrict__ Wqkv, const float* __restrict__ bqkv,
                              const float* __restrict__ Wb, const float* __restrict__ bb) {
    int g = blockIdx.x;    // 0..127 (k/v rows)
    int k = blockIdx.y;    // edge type
    int cp = threadIdx.x;  // 0..63
    const float* Wq = Wqkv + k * 12288 + (64 + g) * 64;
    const float* Wbk = Wb + k * 4096;
    float acc = 0.f;
#pragma unroll 8
    for (int c = 0; c < 64; c++) acc += Wq[c] * Wbk[c * 64 + cp];
    d_Wf[k * 8192 + g * 64 + cp] = acc;
    if (cp == 0) {
        float b = bqkv[k * 192 + 64 + g];
        for (int c = 0; c < 64; c++) b += Wq[c] * bb[k * 64 + c];
        d_bfv[k * 128 + g] = b;
    }
}

// ---------------- per-node table GEMM: Y[M][NCOL] = X[M][64] @ W[NCOL][64]^T + b ----------------
// sel: 0 -> d_qkvA0, 1 -> d_qkvA1, 2 -> d_kv0 (fused W), 3 -> d_kv1 (fused W)
template <int NCOL>
__global__ void table_gemm(const float* __restrict__ X, const float* __restrict__ Wp,
                           const float* __restrict__ bp, int sel) {
    constexpr int HALF = NCOL / 2;
    constexpr int HP = HALF + 1;
    constexpr int CPT = HALF / 16;  // cols per thread per half
    __shared__ float sX[64 * 68];
    __shared__ float sWT[64 * HP];
    __shared__ float sB[NCOL];

    float* Y = (sel == 0) ? d_qkvA0 : (sel == 1) ? d_qkvA1 : (sel == 2) ? d_kv0 : d_kv1;
    const float* W = (sel < 2) ? Wp : d_Wf + (sel - 2) * 8192;
    const float* bias = (sel < 2) ? bp : d_bfv + (sel - 2) * 128;

    int tid = threadIdx.x;
    int row0 = blockIdx.x * 64;

    for (int i = tid; i < 64 * 16; i += 128) {
        int r = i >> 4, j = i & 15;
        ((float4*)(sX + r * 68))[j] = ((const float4*)(X + (size_t)(row0 + r) * 64))[j];
    }
    for (int i = tid; i < NCOL; i += 128) sB[i] = bias[i];

    int tx = tid & 15, ty = tid >> 4;
    for (int hh = 0; hh < 2; hh++) {
        int h0 = hh * HALF;
        __syncthreads();
        for (int i = tid; i < HALF * 64; i += 128) {
            int c = i >> 6, kk = i & 63;
            sWT[kk * HP + c] = W[(h0 + c) * 64 + kk];
        }
        __syncthreads();
        float acc[8][CPT];
#pragma unroll
        for (int i = 0; i < 8; i++)
#pragma unroll
            for (int j = 0; j < CPT; j++) acc[i][j] = 0.f;
#pragma unroll 4
        for (int kk = 0; kk < 64; kk++) {
            float xa[8];
#pragma unroll
            for (int i = 0; i < 8; i++) xa[i] = sX[(ty * 8 + i) * 68 + kk];
#pragma unroll
            for (int j = 0; j < CPT; j++) {
                float w = sWT[kk * HP + tx + 16 * j];
#pragma unroll
                for (int i = 0; i < 8; i++) acc[i][j] += xa[i] * w;
            }
        }
#pragma unroll
        for (int i = 0; i < 8; i++) {
            size_t r = (size_t)(row0 + ty * 8 + i);
#pragma unroll
            for (int j = 0; j < CPT; j++) {
                int c = h0 + tx + 16 * j;
                Y[r * NCOL + c] = acc[i][j] + sB[c];
            }
        }
    }
}

// ---------------- fused per-edge transformer ----------------
// 256 threads = 2 edges per block; gridDim.y = edge type. Dynamic smem layout (floats):
//  [0)      smWo 64x68      (4352)
//  [4352)   smW1 64x68
//  [8704)   smW2 64x68
//  [13056)  vec: bo|bf1|bf2|g1|be1|g2|be2  (7*64 = 448)
//  [13504)  per-sub (2264 ea): qi 4x196 | kvj 4x132 | sx 4x68 | sa 128 | so 4x68 | su 4x68 | stats 8
__global__ void edge_kernel(const int* __restrict__ e_ba, const int* __restrict__ e_aa,
                            const float* __restrict__ x_dst,
                            const float* __restrict__ WoB, const float* __restrict__ boB,
                            const float* __restrict__ g1B, const float* __restrict__ be1B,
                            const float* __restrict__ W1B, const float* __restrict__ bf1B,
                            const float* __restrict__ W2B, const float* __restrict__ bf2B,
                            const float* __restrict__ g2B, const float* __restrict__ be2B) {
    extern __shared__ float sm[];
    float* smWo = sm;
    float* smW1 = sm + 4352;
    float* smW2 = sm + 8704;
    float* vec = sm + 13056;

    int k = blockIdx.y;
    const int* eidx = k ? e_aa : e_ba;
    const float* Wo = WoB + k * 4096;
    const float* W1 = W1B + k * 4096;
    const float* W2 = W2B + k * 4096;

    int tid = threadIdx.x;
    int sub = tid >> 7;
    int t128 = tid & 127;
    float* base = sm + 13504 + sub * 2264;
    float* qi = base;             // 4 x 196 (192 used)
    float* kvj = base + 784;      // 4 x 132 (128 used)
    float* sx = base + 1312;      // 4 x 68 : xi, then x1
    float* sa = base + 1584;      // [h][s][t] 4*4*8
    float* so = base + 1712;      // 4 x 68 : o, then z
    float* su = base + 1984;      // 4 x 68
    float* stats = base + 2256;   // [s][mean,rstd]

    const float* qkv_tab = (k == 0) ? d_qkvA0 : d_qkvA1;
    const float* kv_tab = (k == 0) ? d_kv0 : d_kv1;
    float* sum_tab = (k == 0) ? d_sum0 : d_sum1;
    float* cnt_tab = (k == 0) ? d_cnt0 : d_cnt1;

    // weights -> shared (once per block)
    for (int i = tid; i < 1024; i += 256) {
        int r = i >> 4, j = i & 15;
        ((float4*)(smWo + r * 68))[j] = ((const float4*)Wo)[i];
        ((float4*)(smW1 + r * 68))[j] = ((const float4*)W1)[i];
        ((float4*)(smW2 + r * 68))[j] = ((const float4*)W2)[i];
    }
    if (tid < 64) {
        vec[tid] = boB[k * 64 + tid];
        vec[64 + tid] = bf1B[k * 64 + tid];
        vec[128 + tid] = bf2B[k * 64 + tid];
        vec[192 + tid] = g1B[k * 64 + tid];
        vec[256 + tid] = be1B[k * 64 + tid];
        vec[320 + tid] = g2B[k * 64 + tid];
        vec[384 + tid] = be2B[k * 64 + tid];
    }

    int lane = t128 & 31;
    int warp = t128 >> 5;
    int cc = t128 & 63;
    int s0 = t128 >> 6;  // thread handles rows s0 and s0+2

    for (int e0 = blockIdx.x * 2; e0 < NE; e0 += gridDim.x * 2) {
        int ei = e0 + sub;
        int src = eidx[ei];
        int dst = eidx[NE + ei];
        __syncthreads();  // previous iteration fully drained (also covers weight preload)

        // ---- gather node data ----
        {
            const float4* gq = (const float4*)(qkv_tab + (size_t)dst * 768);
            const float4* gk = (const float4*)(kv_tab + (size_t)src * 512);
            const float4* gx = (const float4*)(x_dst + (size_t)dst * 256);
            for (int i = t128; i < 192; i += 128) {
                int t = i / 48, j = i - t * 48;
                ((float4*)(qi + t * 196))[j] = gq[i];
            }
            { int t = t128 >> 5, j = t128 & 31; ((float4*)(kvj + t * 132))[j] = gk[t128]; }
            if (t128 < 64) { int t = t128 >> 4, j = t128 & 15; ((float4*)(sx + t * 68))[j] = gx[t128]; }
        }
        __syncthreads();

        // ---- attention scores + softmax (warp=head; lane: s=lane/8, t=lane%8) ----
        {
            int h = warp, s = lane >> 3, t = lane & 7;
            const float4* qp = (const float4*)(qi + s * 196 + h * 16);
            const float4* kp = (t < 4) ? (const float4*)(qi + t * 196 + 64 + h * 16)
                                       : (const float4*)(kvj + (t - 4) * 132 + h * 16);
            float acc = 0.f;
#pragma unroll
            for (int j = 0; j < 4; j++) {
                float4 a = qp[j], b = kp[j];
                acc += a.x * b.x + a.y * b.y + a.z * b.z + a.w * b.w;
            }
            acc *= 0.25f;  // 1/sqrt(16)
            float mx = acc;
            for (int o = 4; o; o >>= 1) mx = fmaxf(mx, __shfl_xor_sync(0xffffffffu, mx, o, 8));
            float ex = __expf(acc - mx);
            float sume = ex;
            for (int o = 4; o; o >>= 1) sume += __shfl_xor_sync(0xffffffffu, sume, o, 8);
            sa[h * 32 + s * 8 + t] = ex / sume;
        }
        __syncthreads();

        // ---- o = a @ v  (only rows 0..3 needed) ----
        {
#pragma unroll
            for (int p = 0; p < 2; p++) {
                int s = s0 + p * 2;
                const float* ar = sa + (cc >> 4) * 32 + s * 8;
                float acc = 0.f;
#pragma unroll
                for (int t = 0; t < 4; t++) acc += ar[t] * qi[t * 196 + 128 + cc];
#pragma unroll
                for (int t = 0; t < 4; t++) acc += ar[4 + t] * kvj[t * 132 + 64 + cc];
                so[s * 68 + cc] = acc;
            }
        }
        __syncthreads();

        // ---- u = xi + o @ Wo^T + bo ----
        {
            const float4* wr = (const float4*)(smWo + cc * 68);
            const float4* o0 = (const float4*)(so + s0 * 68);
            const float4* o1 = (const float4*)(so + (s0 + 2) * 68);
            float a0 = sx[s0 * 68 + cc] + vec[cc];
            float a1 = sx[(s0 + 2) * 68 + cc] + vec[cc];
#pragma unroll
            for (int j = 0; j < 16; j++) {
                float4 w = wr[j], p = o0[j], q = o1[j];
                a0 += w.x * p.x + w.y * p.y + w.z * p.z + w.w * p.w;
                a1 += w.x * q.x + w.y * q.y + w.z * q.z + w.w * q.w;
            }
            su[s0 * 68 + cc] = a0;
            su[(s0 + 2) * 68 + cc] = a1;
        }
        __syncthreads();

        // ---- LN1 stats (warp per row) ----
        {
            float v1 = su[warp * 68 + lane], v2 = su[warp * 68 + lane + 32];
            float s = v1 + v2, ss = v1 * v1 + v2 * v2;
            for (int o = 16; o; o >>= 1) {
                s += __shfl_xor_sync(~0u, s, o);
                ss += __shfl_xor_sync(~0u, ss, o);
            }
            if (lane == 0) {
                float mean = s * 0.015625f;
                float var = ss * 0.015625f - mean * mean;
                stats[warp * 2] = mean;
                stats[warp * 2 + 1] = rsqrtf(var + 1e-5f);
            }
        }
        __syncthreads();

        // ---- normalize -> x1 (into sx) ----
        {
#pragma unroll
            for (int p = 0; p < 2; p++) {
                int s = s0 + p * 2;
                sx[s * 68 + cc] =
                    (su[s * 68 + cc] - stats[s * 2]) * stats[s * 2 + 1] * vec[192 + cc] + vec[256 + cc];
            }
        }
        __syncthreads();

        // ---- FF1: z = relu(x1 @ W1^T + bf1) (into so) ----
        {
            const float4* wr = (const float4*)(smW1 + cc * 68);
            const float4* x0 = (const float4*)(sx + s0 * 68);
            const float4* x1 = (const float4*)(sx + (s0 + 2) * 68);
            float a0 = vec[64 + cc], a1 = vec[64 + cc];
#pragma unroll
            for (int j = 0; j < 16; j++) {
                float4 w = wr[j], p = x0[j], q = x1[j];
                a0 += w.x * p.x + w.y * p.y + w.z * p.z + w.w * p.w;
                a1 += w.x * q.x + w.y * q.y + w.z * q.z + w.w * q.w;
            }
            so[s0 * 68 + cc] = fmaxf(a0, 0.f);
            so[(s0 + 2) * 68 + cc] = fmaxf(a1, 0.f);
        }
        __syncthreads();

        // ---- FF2 + residual -> su ----
        {
            const float4* wr = (const float4*)(smW2 + cc * 68);
            const float4* z0 = (const float4*)(so + s0 * 68);
            const float4* z1 = (const float4*)(so + (s0 + 2) * 68);
            float a0 = sx[s0 * 68 + cc] + vec[128 + cc];
            float a1 = sx[(s0 + 2) * 68 + cc] + vec[128 + cc];
#pragma unroll
            for (int j = 0; j < 16; j++) {
                float4 w = wr[j], p = z0[j], q = z1[j];
                a0 += w.x * p.x + w.y * p.y + w.z * p.z + w.w * p.w;
                a1 += w.x * q.x + w.y * q.y + w.z * q.z + w.w * q.w;
            }
            su[s0 * 68 + cc] = a0;
            su[(s0 + 2) * 68 + cc] = a1;
        }
        __syncthreads();

        // ---- LN2 stats ----
        {
            float v1 = su[warp * 68 + lane], v2 = su[warp * 68 + lane + 32];
            float s = v1 + v2, ss = v1 * v1 + v2 * v2;
            for (int o = 16; o; o >>= 1) {
                s += __shfl_xor_sync(~0u, s, o);
                ss += __shfl_xor_sync(~0u, ss, o);
            }
            if (lane == 0) {
                float mean = s * 0.015625f;
                float var = ss * 0.015625f - mean * mean;
                stats[warp * 2] = mean;
                stats[warp * 2 + 1] = rsqrtf(var + 1e-5f);
            }
        }
        __syncthreads();

        // ---- normalize + atomic scatter ----
        {
            float* dstp = sum_tab + (size_t)dst * 256;
#pragma unroll
            for (int p = 0; p < 2; p++) {
                int s = s0 + p * 2;
                float y =
                    (su[s * 68 + cc] - stats[s * 2]) * stats[s * 2 + 1] * vec[320 + cc] + vec[384 + cc];
                atomicAdd(dstp + s * 64 + cc, y);
            }
            if (t128 == 0) atomicAdd(cnt_tab + dst, 1.0f);
        }
    }
}

// ---------------- finalize: mean across types, output proj, sum over T, softmax ----------------
__global__ void finalize_kernel(const float* __restrict__ Wout, const float* __restrict__ bout,
                                float* __restrict__ out) {
    __shared__ float sW[32 * 65];
    __shared__ float sz[4][64];
    int tid = threadIdx.x;
    for (int i = tid; i < 2048; i += 128) sW[(i >> 6) * 65 + (i & 63)] = Wout[i];
    int nb = tid >> 5, lane = tid & 31;
    int n = blockIdx.x * 4 + nb;

    float c0 = d_cnt0[n], c1 = d_cnt1[n];
    float i0 = 0.5f / fmaxf(c0, 1.f);
    float i1 = 0.5f / fmaxf(c1, 1.f);
    const float* sp0 = d_sum0 + (size_t)n * 256;
    const float* sp1 = d_sum1 + (size_t)n * 256;
    for (int c = lane; c < 64; c += 32) {
        float a = 0.f, b = 0.f;
#pragma unroll
        for (int t = 0; t < 4; t++) { a += sp0[t * 64 + c]; b += sp1[t * 64 + c]; }
        sz[nb][c] = a * i0 + b * i1;
    }
    __syncthreads();

    float acc = 4.f * bout[lane];
    const float* wr = sW + lane * 65;
    const float* zz = sz[nb];
#pragma unroll 8
    for (int c = 0; c < 64; c++) acc += zz[c] * wr[c];

    float mx = acc;
    for (int o = 16; o; o >>= 1) mx = fmaxf(mx, __shfl_xor_sync(~0u, mx, o));
    float ex = __expf(acc - mx);
    float s = ex;
    for (int o = 16; o; o >>= 1) s += __shfl_xor_sync(~0u, s, o);
    out[(size_t)n * 32 + lane] = ex / s;
}

// ---------------- host ----------------
extern "C" void kernel_launch(void* const* d_in, const int* in_sizes, int n_in,
                              void* d_out, int out_size) {
    const float* x_A = (const float*)d_in[0];
    const float* x_B = (const float*)d_in[1];
    const int* e_ba = (const int*)d_in[2];
    const int* e_aa = (const int*)d_in[3];
    const float* Wb = (const float*)d_in[4];
    const float* bb = (const float*)d_in[5];
    const float* Wqkv = (const float*)d_in[6];
    const float* bqkv = (const float*)d_in[7];
    const float* Wo = (const float*)d_in[8];
    const float* bo = (const float*)d_in[9];
    const float* g1 = (const float*)d_in[10];
    const float* be1 = (const float*)d_in[11];
    const float* W1 = (const float*)d_in[12];
    const float* bf1 = (const float*)d_in[13];
    const float* W2 = (const float*)d_in[14];
    const float* bf2 = (const float*)d_in[15];
    const float* g2 = (const float*)d_in[16];
    const float* be2 = (const float*)d_in[17];
    const float* Wout = (const float*)d_in[18];
    const float* bout = (const float*)d_in[19];
    float* out = (float*)d_out;

    const int EDGE_SMEM = 18032 * 4;  // 72128 B
    cudaFuncSetAttribute(edge_kernel, cudaFuncAttributeMaxDynamicSharedMemorySize, EDGE_SMEM);

    zero_kernel<<<2048, 256>>>();
    fuse_w_kernel<<<dim3(128, 2), 64>>>(Wqkv, bqkv, Wb, bb);
    table_gemm<192><<<2500, 128>>>(x_A, Wqkv, bqkv, 0);
    table_gemm<192><<<2500, 128>>>(x_A, Wqkv + 12288, bqkv + 192, 1);
    table_gemm<128><<<2500, 128>>>(x_B, nullptr, nullptr, 2);
    table_gemm<128><<<2500, 128>>>(x_A, nullptr, nullptr, 3);
    edge_kernel<<<dim3(2048, 2), 256, EDGE_SMEM>>>(e_ba, e_aa, x_A, Wo, bo, g1, be1, W1, bf1, W2,
                                                   bf2, g2, be2);
    finalize_kernel<<<10000, 128>>>(Wout, bout, out);
}

// round 4
// speedup vs baseline: 1.0493x; 1.0493x over previous
#include <cuda_runtime.h>
#include <cstdint>
#include <cstddef>

static const int NA = 40000;
static const int NE = 150000;

// ---------------- device scratch (static, no allocation) ----------------
__device__ float d_qkvA0[40000 * 768];   // type0 dst qkv table [n][t][192]
__device__ float d_qkvA1[40000 * 768];   // type1 dst qkv table
__device__ float d_kv0[40000 * 512];     // type0 src kv table (B nodes, fused b_proj)
__device__ float d_kv1[40000 * 512];     // type1 src kv table (A nodes, fused b_proj)
__device__ float d_sum0[40000 * 256];
__device__ float d_sum1[40000 * 256];
__device__ float d_cnt0[40000];
__device__ float d_cnt1[40000];
__device__ float d_Wf[2 * 128 * 64];     // fused (Wqkv_kv @ Wb)
__device__ float d_bfv[2 * 128];         // fused bias

// ---------------- fused weight: Wf[g][c'] = sum_c Wqkv[64+g][c] * Wb[c][c'] ----------------
__global__ void fuse_w_kernel(const float* __restrict__ Wqkv, const float* __restrict__ bqkv,
                              const float* __restrict__ Wb, const float* __restrict__ bb) {
    int g = blockIdx.x;    // 0..127 (k/v rows)
    int k = blockIdx.y;    // edge type
    int cp = threadIdx.x;  // 0..63
    const float* Wq = Wqkv + k * 12288 + (64 + g) * 64;
    const float* Wbk = Wb + k * 4096;
    float acc = 0.f;
#pragma unroll 8
    for (int c = 0; c < 64; c++) acc += Wq[c] * Wbk[c * 64 + cp];
    d_Wf[k * 8192 + g * 64 + cp] = acc;
    if (cp == 0) {
        float b = bqkv[k * 192 + 64 + g];
        for (int c = 0; c < 64; c++) b += Wq[c] * bb[k * 64 + c];
        d_bfv[k * 128 + g] = b;
    }
}

// ---------------- per-node table GEMM: Y[M][NCOL] = X[M][64] @ W[NCOL][64]^T + b ----------------
// blockIdx.y selects edge type; both types run concurrently in one launch.
template <int NCOL>
__global__ void table_gemm(const float* __restrict__ X0, const float* __restrict__ X1,
                           const float* __restrict__ Wp, const float* __restrict__ bp) {
    constexpr int HALF = NCOL / 2;
    constexpr int HP = HALF + 1;
    constexpr int CPT = HALF / 16;  // cols per thread per half
    __shared__ float sX[64 * 68];
    __shared__ float sWT[64 * HP];
    __shared__ float sB[NCOL];

    int yb = blockIdx.y;
    float* Y;
    const float* X;
    const float* W;
    const float* bias;
    if constexpr (NCOL == 192) {
        Y = yb ? d_qkvA1 : d_qkvA0;
        X = X0;
        W = Wp + yb * 12288;
        bias = bp + yb * 192;
    } else {
        Y = yb ? d_kv1 : d_kv0;
        X = yb ? X1 : X0;
        W = d_Wf + yb * 8192;
        bias = d_bfv + yb * 128;
    }

    int tid = threadIdx.x;
    int row0 = blockIdx.x * 64;

    for (int i = tid; i < 64 * 16; i += 128) {
        int r = i >> 4, j = i & 15;
        ((float4*)(sX + r * 68))[j] = ((const float4*)(X + (size_t)(row0 + r) * 64))[j];
    }
    for (int i = tid; i < NCOL; i += 128) sB[i] = bias[i];

    int tx = tid & 15, ty = tid >> 4;
    for (int hh = 0; hh < 2; hh++) {
        int h0 = hh * HALF;
        __syncthreads();
        for (int i = tid; i < HALF * 64; i += 128) {
            int c = i >> 6, kk = i & 63;
            sWT[kk * HP + c] = W[(h0 + c) * 64 + kk];
        }
        __syncthreads();
        float acc[8][CPT];
#pragma unroll
        for (int i = 0; i < 8; i++)
#pragma unroll
            for (int j = 0; j < CPT; j++) acc[i][j] = 0.f;
#pragma unroll 4
        for (int kk = 0; kk < 64; kk++) {
            float xa[8];
#pragma unroll
            for (int i = 0; i < 8; i++) xa[i] = sX[(ty * 8 + i) * 68 + kk];
#pragma unroll
            for (int j = 0; j < CPT; j++) {
                float w = sWT[kk * HP + tx + 16 * j];
#pragma unroll
                for (int i = 0; i < 8; i++) acc[i][j] += xa[i] * w;
            }
        }
#pragma unroll
        for (int i = 0; i < 8; i++) {
            size_t r = (size_t)(row0 + ty * 8 + i);
#pragma unroll
            for (int j = 0; j < CPT; j++) {
                int c = h0 + tx + 16 * j;
                Y[r * NCOL + c] = acc[i][j] + sB[c];
            }
        }
    }
}

// ---------------- fused per-edge transformer ----------------
// 256 threads = 4 independent 64-thread groups, each processing 2 edges per
// iteration (R=8 rows per weight load). Group-local named barriers only.
// Dynamic smem (floats):
//  [0)       swizzled weights: Wo|W1|W2, each 64x64 f4-XOR-swizzled (3*4096)
//  [12288)   vec: bo|bf1|bf2|g1|be1|g2|be2  (448)
//  [12736)   8 edge buffers, stride 1936:
//            qi 768 | kvj 512 | sx 256 | sa 128 | so 256 | stats 8
#define EB_QI 0
#define EB_KV 768
#define EB_SX 1280
#define EB_SA 1536
#define EB_SO 1664
#define EB_ST 1920
#define EB_STRIDE 1936

__device__ __forceinline__ void gather_edge(float* eb, const float* gq, const float* gk,
                                            const float* gx, int cc) {
    float4* d = (float4*)eb;
    const float4* q4 = (const float4*)gq;
    const float4* k4 = (const float4*)gk;
    const float4* x4 = (const float4*)gx;
#pragma unroll
    for (int i = 0; i < 3; i++) d[cc + 64 * i] = q4[cc + 64 * i];
#pragma unroll
    for (int i = 0; i < 2; i++) d[192 + cc + 64 * i] = k4[cc + 64 * i];
    d[320 + cc] = x4[cc];
}

// acc[p][s] += sum_k W[m][cc][k] * x_p[s][k]   (x rows are 16 float4 each)
__device__ __forceinline__ void gemv64(const float* smW, int m, int cc, const float* x0,
                                       const float* x1, float acc[2][4]) {
    const float4* wb = ((const float4*)smW) + m * 1024 + cc * 16;
    const float4* xr0 = (const float4*)x0;
    const float4* xr1 = (const float4*)x1;
#pragma unroll
    for (int j = 0; j < 16; j++) {
        float4 w = wb[(j + cc) & 15];
#pragma unroll
        for (int s = 0; s < 4; s++) {
            float4 a = xr0[s * 16 + j];
            acc[0][s] += w.x * a.x + w.y * a.y + w.z * a.z + w.w * a.w;
            float4 b = xr1[s * 16 + j];
            acc[1][s] += w.x * b.x + w.y * b.y + w.z * b.z + w.w * b.w;
        }
    }
}

__device__ __forceinline__ void ln_stats(float* eb, int lane) {
#pragma unroll
    for (int s = 0; s < 4; s++) {
        float v1 = eb[EB_SX + s * 64 + lane];
        float v2 = eb[EB_SX + s * 64 + lane + 32];
        float sum = v1 + v2, ss = v1 * v1 + v2 * v2;
#pragma unroll
        for (int o = 16; o; o >>= 1) {
            sum += __shfl_xor_sync(~0u, sum, o);
            ss += __shfl_xor_sync(~0u, ss, o);
        }
        if (lane == 0) {
            float mean = sum * 0.015625f;
            float var = ss * 0.015625f - mean * mean;
            eb[EB_ST + s * 2] = mean;
            eb[EB_ST + s * 2 + 1] = rsqrtf(var + 1e-5f);
        }
    }
}

__global__ __launch_bounds__(256, 2) void edge_kernel(
    const int* __restrict__ e_ba, const int* __restrict__ e_aa, const float* __restrict__ x_dst,
    const float* __restrict__ WoB, const float* __restrict__ boB, const float* __restrict__ g1B,
    const float* __restrict__ be1B, const float* __restrict__ W1B, const float* __restrict__ bf1B,
    const float* __restrict__ W2B, const float* __restrict__ bf2B, const float* __restrict__ g2B,
    const float* __restrict__ be2B) {
    extern __shared__ float sm[];
    float* vec = sm + 12288;
    float* ebase = sm + 12736;

    const int k = blockIdx.y;
    const int* eidx = k ? e_aa : e_ba;
    int tid = threadIdx.x;
    int g = tid >> 6;
    int cc = tid & 63;
    int lane = tid & 31;
    int w2 = (tid >> 5) & 1;

    // --- weight preload (XOR-swizzled float4 layout), once per block ---
    {
        const float* Wsrc0 = WoB + k * 4096;
        const float* Wsrc1 = W1B + k * 4096;
        const float* Wsrc2 = W2B + k * 4096;
        for (int idx = tid; idx < 3072; idx += 256) {
            int m = idx >> 10, rem = idx & 1023, r = rem >> 4, j = rem & 15;
            const float* src = (m == 0) ? Wsrc0 : (m == 1) ? Wsrc1 : Wsrc2;
            ((float4*)sm)[m * 1024 + r * 16 + ((j + r) & 15)] = ((const float4*)src)[rem];
        }
        if (tid < 64) {
            vec[tid] = boB[k * 64 + tid];
            vec[64 + tid] = bf1B[k * 64 + tid];
            vec[128 + tid] = bf2B[k * 64 + tid];
            vec[192 + tid] = g1B[k * 64 + tid];
            vec[256 + tid] = be1B[k * 64 + tid];
            vec[320 + tid] = g2B[k * 64 + tid];
            vec[384 + tid] = be2B[k * 64 + tid];
        }
    }
    const float* qkv_tab = k ? d_qkvA1 : d_qkvA0;
    const float* kv_tab = k ? d_kv1 : d_kv0;
    float* sum_tab = k ? d_sum1 : d_sum0;
    float* cnt_tab = k ? d_cnt1 : d_cnt0;
    __syncthreads();

    float* eb0 = ebase + (size_t)(g * 2 + 0) * EB_STRIDE;
    float* eb1 = ebase + (size_t)(g * 2 + 1) * EB_STRIDE;

#define BARG() asm volatile("bar.sync %0, 64;" ::"r"(g + 1) : "memory")

    for (int e0 = blockIdx.x * 8; e0 < NE; e0 += gridDim.x * 8) {
        int ea = e0 + g * 2, eb_i = ea + 1;
        int srcA = eidx[ea], dstA = eidx[NE + ea];
        int srcB = eidx[eb_i], dstB = eidx[NE + eb_i];
        BARG();  // previous iteration fully drained before overwriting buffers

        // ---- gather node data (group-cooperative, contiguous copies) ----
        gather_edge(eb0, qkv_tab + (size_t)dstA * 768, kv_tab + (size_t)srcA * 512,
                    x_dst + (size_t)dstA * 256, cc);
        gather_edge(eb1, qkv_tab + (size_t)dstB * 768, kv_tab + (size_t)srcB * 512,
                    x_dst + (size_t)dstB * 256, cc);
        BARG();

        // ---- attention scores + softmax (warp w2 handles its edge, all 4 heads) ----
        {
            float* eb = w2 ? eb1 : eb0;
            int s = lane >> 3, t = lane & 7;
#pragma unroll
            for (int h = 0; h < 4; h++) {
                const float4* qp = (const float4*)(eb + s * 192 + h * 16);
                const float4* kp = (t < 4) ? (const float4*)(eb + t * 192 + 64 + h * 16)
                                           : (const float4*)(eb + EB_KV + (t - 4) * 128 + h * 16);
                float acc = 0.f;
#pragma unroll
                for (int j = 0; j < 4; j++) {
                    float4 a = qp[j], b = kp[j];
                    acc += a.x * b.x + a.y * b.y + a.z * b.z + a.w * b.w;
                }
                acc *= 0.25f;  // 1/sqrt(16)
                float mx = acc;
#pragma unroll
                for (int o = 4; o; o >>= 1) mx = fmaxf(mx, __shfl_xor_sync(~0u, mx, o, 8));
                float ex = __expf(acc - mx);
                float se = ex;
#pragma unroll
                for (int o = 4; o; o >>= 1) se += __shfl_xor_sync(~0u, se, o, 8);
                eb[EB_SA + h * 32 + lane] = ex / se;
            }
        }
        BARG();

        // ---- o = a @ v  (rows 0..3 only) -> so ----
        {
            int h = cc >> 4;
#pragma unroll
            for (int p = 0; p < 2; p++) {
                float* eb = p ? eb1 : eb0;
                const float* ap = eb + EB_SA + h * 32;
                const float* vq = eb + 128 + cc;           // qi v-section, stride 192
                const float* vk = eb + EB_KV + 64 + cc;    // kvj v-section, stride 128
#pragma unroll
                for (int s = 0; s < 4; s++) {
                    const float* ar = ap + s * 8;
                    float acc = ar[0] * vq[0] + ar[1] * vq[192] + ar[2] * vq[384] +
                                ar[3] * vq[576] + ar[4] * vk[0] + ar[5] * vk[128] +
                                ar[6] * vk[256] + ar[7] * vk[384];
                    eb[EB_SO + s * 64 + cc] = acc;
                }
            }
        }
        BARG();

        // ---- u = xi + o @ Wo^T + bo  (in-place into sx) ----
        {
            float acc[2][4];
#pragma unroll
            for (int s = 0; s < 4; s++) {
                acc[0][s] = eb0[EB_SX + s * 64 + cc] + vec[cc];
                acc[1][s] = eb1[EB_SX + s * 64 + cc] + vec[cc];
            }
            gemv64(sm, 0, cc, eb0 + EB_SO, eb1 + EB_SO, acc);
#pragma unroll
            for (int s = 0; s < 4; s++) {
                eb0[EB_SX + s * 64 + cc] = acc[0][s];
                eb1[EB_SX + s * 64 + cc] = acc[1][s];
            }
        }
        BARG();
        ln_stats(w2 ? eb1 : eb0, lane);
        BARG();

        // ---- normalize -> x1 (in place) ----
#pragma unroll
        for (int p = 0; p < 2; p++) {
            float* eb = p ? eb1 : eb0;
#pragma unroll
            for (int s = 0; s < 4; s++) {
                int i = EB_SX + s * 64 + cc;
                eb[i] = (eb[i] - eb[EB_ST + s * 2]) * eb[EB_ST + s * 2 + 1] * vec[192 + cc] +
                        vec[256 + cc];
            }
        }
        BARG();

        // ---- FF1: z = relu(x1 @ W1^T + bf1) -> so ----
        {
            float acc[2][4];
#pragma unroll
            for (int s = 0; s < 4; s++) acc[0][s] = acc[1][s] = vec[64 + cc];
            gemv64(sm, 1, cc, eb0 + EB_SX, eb1 + EB_SX, acc);
#pragma unroll
            for (int s = 0; s < 4; s++) {
                eb0[EB_SO + s * 64 + cc] = fmaxf(acc[0][s], 0.f);
                eb1[EB_SO + s * 64 + cc] = fmaxf(acc[1][s], 0.f);
            }
        }
        BARG();

        // ---- FF2 + residual (in-place into sx) ----
        {
            float acc[2][4];
#pragma unroll
            for (int s = 0; s < 4; s++) {
                acc[0][s] = eb0[EB_SX + s * 64 + cc] + vec[128 + cc];
                acc[1][s] = eb1[EB_SX + s * 64 + cc] + vec[128 + cc];
            }
            gemv64(sm, 2, cc, eb0 + EB_SO, eb1 + EB_SO, acc);
#pragma unroll
            for (int s = 0; s < 4; s++) {
                eb0[EB_SX + s * 64 + cc] = acc[0][s];
                eb1[EB_SX + s * 64 + cc] = acc[1][s];
            }
        }
        BARG();
        ln_stats(w2 ? eb1 : eb0, lane);
        BARG();

        // ---- final normalize + atomic scatter ----
#pragma unroll
        for (int p = 0; p < 2; p++) {
            float* eb = p ? eb1 : eb0;
            int dst = p ? dstB : dstA;
            float* outp = sum_tab + (size_t)dst * 256;
#pragma unroll
            for (int s = 0; s < 4; s++) {
                float y = (eb[EB_SX + s * 64 + cc] - eb[EB_ST + s * 2]) *
                              eb[EB_ST + s * 2 + 1] * vec[320 + cc] +
                          vec[384 + cc];
                atomicAdd(outp + s * 64 + cc, y);
            }
        }
        if (cc == 0) atomicAdd(cnt_tab + dstA, 1.0f);
        if (cc == 32) atomicAdd(cnt_tab + dstB, 1.0f);
    }
#undef BARG
}

// ---------------- finalize: mean across types, output proj, sum over T, softmax ----------------
__global__ void finalize_kernel(const float* __restrict__ Wout, const float* __restrict__ bout,
                                float* __restrict__ out) {
    __shared__ float sW[32 * 65];
    __shared__ float sz[4][64];
    int tid = threadIdx.x;
    for (int i = tid; i < 2048; i += 128) sW[(i >> 6) * 65 + (i & 63)] = Wout[i];
    int nb = tid >> 5, lane = tid & 31;
    int n = blockIdx.x * 4 + nb;

    float c0 = d_cnt0[n], c1 = d_cnt1[n];
    float i0 = 0.5f / fmaxf(c0, 1.f);
    float i1 = 0.5f / fmaxf(c1, 1.f);
    const float* sp0 = d_sum0 + (size_t)n * 256;
    const float* sp1 = d_sum1 + (size_t)n * 256;
    for (int c = lane; c < 64; c += 32) {
        float a = 0.f, b = 0.f;
#pragma unroll
        for (int t = 0; t < 4; t++) { a += sp0[t * 64 + c]; b += sp1[t * 64 + c]; }
        sz[nb][c] = a * i0 + b * i1;
    }
    __syncthreads();

    float acc = 4.f * bout[lane];
    const float* wr = sW + lane * 65;
    const float* zz = sz[nb];
#pragma unroll 8
    for (int c = 0; c < 64; c++) acc += zz[c] * wr[c];

    float mx = acc;
    for (int o = 16; o; o >>= 1) mx = fmaxf(mx, __shfl_xor_sync(~0u, mx, o));
    float ex = __expf(acc - mx);
    float s = ex;
    for (int o = 16; o; o >>= 1) s += __shfl_xor_sync(~0u, s, o);
    out[(size_t)n * 32 + lane] = ex / s;
}

// ---------------- host ----------------
extern "C" void kernel_launch(void* const* d_in, const int* in_sizes, int n_in,
                              void* d_out, int out_size) {
    const float* x_A = (const float*)d_in[0];
    const float* x_B = (const float*)d_in[1];
    const int* e_ba = (const int*)d_in[2];
    const int* e_aa = (const int*)d_in[3];
    const float* Wb = (const float*)d_in[4];
    const float* bb = (const float*)d_in[5];
    const float* Wqkv = (const float*)d_in[6];
    const float* bqkv = (const float*)d_in[7];
    const float* Wo = (const float*)d_in[8];
    const float* bo = (const float*)d_in[9];
    const float* g1 = (const float*)d_in[10];
    const float* be1 = (const float*)d_in[11];
    const float* W1 = (const float*)d_in[12];
    const float* bf1 = (const float*)d_in[13];
    const float* W2 = (const float*)d_in[14];
    const float* bf2 = (const float*)d_in[15];
    const float* g2 = (const float*)d_in[16];
    const float* be2 = (const float*)d_in[17];
    const float* Wout = (const float*)d_in[18];
    const float* bout = (const float*)d_in[19];
    float* out = (float*)d_out;

    const int EDGE_SMEM = 28224 * 4;  // 112896 B -> 2 blocks/SM
    cudaFuncSetAttribute(edge_kernel, cudaFuncAttributeMaxDynamicSharedMemorySize, EDGE_SMEM);

    // zero accumulators via memset nodes
    void *p0, *p1, *pc0, *pc1;
    cudaGetSymbolAddress(&p0, d_sum0);
    cudaGetSymbolAddress(&p1, d_sum1);
    cudaGetSymbolAddress(&pc0, d_cnt0);
    cudaGetSymbolAddress(&pc1, d_cnt1);
    cudaMemsetAsync(p0, 0, (size_t)NA * 256 * 4);
    cudaMemsetAsync(p1, 0, (size_t)NA * 256 * 4);
    cudaMemsetAsync(pc0, 0, (size_t)NA * 4);
    cudaMemsetAsync(pc1, 0, (size_t)NA * 4);

    fuse_w_kernel<<<dim3(128, 2), 64>>>(Wqkv, bqkv, Wb, bb);
    table_gemm<192><<<dim3(2500, 2), 128>>>(x_A, x_A, Wqkv, bqkv);
    table_gemm<128><<<dim3(2500, 2), 128>>>(x_B, x_A, nullptr, nullptr);
    edge_kernel<<<dim3(148, 2), 256, EDGE_SMEM>>>(e_ba, e_aa, x_A, Wo, bo, g1, be1, W1, bf1, W2,
                                                  bf2, g2, be2);
    finalize_kernel<<<10000, 128>>>(Wout, bout, out);
}

// round 5
// speedup vs baseline: 1.1180x; 1.0655x over previous
#include <cuda_runtime.h>
#include <cstdint>
#include <cstddef>

static const int NA = 40000;
static const int NE = 150000;

// ---------------- device scratch (static, no allocation) ----------------
__device__ float d_qkvA0[40000 * 768];   // type0 dst qkv table [n][t][192]
__device__ float d_qkvA1[40000 * 768];   // type1 dst qkv table
__device__ float d_kv0[40000 * 512];     // type0 src kv table (B nodes, fused b_proj)
__device__ float d_kv1[40000 * 512];     // type1 src kv table (A nodes, fused b_proj)
__device__ float d_sum0[40000 * 256];
__device__ float d_sum1[40000 * 256];
__device__ float d_cnt0[40000];
__device__ float d_cnt1[40000];
__device__ float d_Wf[2 * 128 * 64];     // fused (Wqkv_kv @ Wb)
__device__ float d_bfv[2 * 128];         // fused bias

// ---------------- fused weight: Wf[g][c'] = sum_c Wqkv[64+g][c] * Wb[c][c'] ----------------
__global__ void fuse_w_kernel(const float* __restrict__ Wqkv, const float* __restrict__ bqkv,
                              const float* __restrict__ Wb, const float* __restrict__ bb) {
    int g = blockIdx.x;    // 0..127 (k/v rows)
    int k = blockIdx.y;    // edge type
    int cp = threadIdx.x;  // 0..63
    const float* Wq = Wqkv + k * 12288 + (64 + g) * 64;
    const float* Wbk = Wb + k * 4096;
    float acc = 0.f;
#pragma unroll 8
    for (int c = 0; c < 64; c++) acc += Wq[c] * Wbk[c * 64 + cp];
    d_Wf[k * 8192 + g * 64 + cp] = acc;
    if (cp == 0) {
        float b = bqkv[k * 192 + 64 + g];
        for (int c = 0; c < 64; c++) b += Wq[c] * bb[k * 64 + c];
        d_bfv[k * 128 + g] = b;
    }
}

// ---------------- per-node table GEMM body: Y[M][NCOL] = X[M][64] @ W[NCOL][64]^T + b ----------
template <int NCOL>
__device__ __forceinline__ void table_body(float* sm, const float* __restrict__ X,
                                           const float* __restrict__ W,
                                           const float* __restrict__ bias, float* __restrict__ Y,
                                           int row0) {
    constexpr int HALF = NCOL / 2;
    constexpr int HP = HALF + 1;
    constexpr int CPT = HALF / 16;
    float* sX = sm;                  // 64*68
    float* sWT = sm + 64 * 68;       // 64*HP
    float* sB = sWT + 64 * HP;       // NCOL

    int tid = threadIdx.x;
    for (int i = tid; i < 64 * 16; i += 128) {
        int r = i >> 4, j = i & 15;
        ((float4*)(sX + r * 68))[j] = ((const float4*)(X + (size_t)(row0 + r) * 64))[j];
    }
    for (int i = tid; i < NCOL; i += 128) sB[i] = bias[i];

    int tx = tid & 15, ty = tid >> 4;
    for (int hh = 0; hh < 2; hh++) {
        int h0 = hh * HALF;
        __syncthreads();
        for (int i = tid; i < HALF * 64; i += 128) {
            int c = i >> 6, kk = i & 63;
            sWT[kk * HP + c] = W[(h0 + c) * 64 + kk];
        }
        __syncthreads();
        float acc[8][CPT];
#pragma unroll
        for (int i = 0; i < 8; i++)
#pragma unroll
            for (int j = 0; j < CPT; j++) acc[i][j] = 0.f;
#pragma unroll 4
        for (int kk = 0; kk < 64; kk++) {
            float xa[8];
#pragma unroll
            for (int i = 0; i < 8; i++) xa[i] = sX[(ty * 8 + i) * 68 + kk];
#pragma unroll
            for (int j = 0; j < CPT; j++) {
                float w = sWT[kk * HP + tx + 16 * j];
#pragma unroll
                for (int i = 0; i < 8; i++) acc[i][j] += xa[i] * w;
            }
        }
#pragma unroll
        for (int i = 0; i < 8; i++) {
            size_t r = (size_t)(row0 + ty * 8 + i);
#pragma unroll
            for (int j = 0; j < CPT; j++) {
                int c = h0 + tx + 16 * j;
                Y[r * NCOL + c] = acc[i][j] + sB[c];
            }
        }
    }
}

// all four node tables in one launch: y=0,1 -> qkv tables; y=2,3 -> kv tables
__global__ void table_all(const float* __restrict__ x_A, const float* __restrict__ x_B,
                          const float* __restrict__ Wqkv, const float* __restrict__ bqkv) {
    extern __shared__ float sm[];
    int yb = blockIdx.y;
    int row0 = blockIdx.x * 64;
    if (yb < 2) {
        table_body<192>(sm, x_A, Wqkv + yb * 12288, bqkv + yb * 192, yb ? d_qkvA1 : d_qkvA0, row0);
    } else {
        int t = yb - 2;
        table_body<128>(sm, t ? x_A : x_B, d_Wf + t * 8192, d_bfv + t * 128, t ? d_kv1 : d_kv0,
                        row0);
    }
}

// ---------------- fused per-edge transformer ----------------
// 256 threads = 4 groups of 2 warps. Each WARP owns one edge per iteration for
// gather/attention/o/LN (warp-local, __syncwarp only); the two warps of a group
// join only for the three 64x64 GEMVs (R=8 rows per weight load).
// smem (floats): [0,12288) swizzled Wo|W1|W2; [12288,12736) vec; then 8 edge
// buffers of stride 1928: EQ 768 | EK 512 | EX 256 | ES 256 | EA 128 | pad
#define EB_EQ 0
#define EB_EK 768
#define EB_EX 1280
#define EB_ES 1536
#define EB_EA 1792
#define EB_STRIDE 1928

// acc[p][s] += sum_k W[m][cc][k] * x_p[s][k]   (x rows are 16 float4 each)
__device__ __forceinline__ void gemv64(const float* smW, int m, int cc, const float* x0,
                                       const float* x1, float acc[2][4]) {
    const float4* wb = ((const float4*)smW) + m * 1024 + cc * 16;
    const float4* xr0 = (const float4*)x0;
    const float4* xr1 = (const float4*)x1;
#pragma unroll
    for (int j = 0; j < 16; j++) {
        float4 w = wb[(j + cc) & 15];
#pragma unroll
        for (int s = 0; s < 4; s++) {
            float4 a = xr0[s * 16 + j];
            acc[0][s] += w.x * a.x + w.y * a.y + w.z * a.z + w.w * a.w;
            float4 b = xr1[s * 16 + j];
            acc[1][s] += w.x * b.x + w.y * b.y + w.z * b.z + w.w * b.w;
        }
    }
}

__global__ __launch_bounds__(256, 2) void edge_kernel(
    const int* __restrict__ e_ba, const int* __restrict__ e_aa, const float* __restrict__ x_dst,
    const float* __restrict__ WoB, const float* __restrict__ boB, const float* __restrict__ g1B,
    const float* __restrict__ be1B, const float* __restrict__ W1B, const float* __restrict__ bf1B,
    const float* __restrict__ W2B, const float* __restrict__ bf2B, const float* __restrict__ g2B,
    const float* __restrict__ be2B) {
    extern __shared__ float sm[];
    float* vec = sm + 12288;
    float* ebase = sm + 12736;

    const int k = blockIdx.y;
    const int* eidx = k ? e_aa : e_ba;
    int tid = threadIdx.x;
    int g = tid >> 6;
    int t64 = tid & 63;
    int w = (tid >> 5) & 1;
    int lane = tid & 31;

    // --- weight preload (XOR-swizzled float4 layout), once per block ---
    {
        const float* Wsrc0 = WoB + k * 4096;
        const float* Wsrc1 = W1B + k * 4096;
        const float* Wsrc2 = W2B + k * 4096;
        for (int idx = tid; idx < 3072; idx += 256) {
            int m = idx >> 10, rem = idx & 1023, r = rem >> 4, j = rem & 15;
            const float* src = (m == 0) ? Wsrc0 : (m == 1) ? Wsrc1 : Wsrc2;
            ((float4*)sm)[m * 1024 + r * 16 + ((j + r) & 15)] = ((const float4*)src)[rem];
        }
        if (tid < 64) {
            vec[tid] = boB[k * 64 + tid];
            vec[64 + tid] = bf1B[k * 64 + tid];
            vec[128 + tid] = bf2B[k * 64 + tid];
            vec[192 + tid] = g1B[k * 64 + tid];
            vec[256 + tid] = be1B[k * 64 + tid];
            vec[320 + tid] = g2B[k * 64 + tid];
            vec[384 + tid] = be2B[k * 64 + tid];
        }
    }
    const float* qkv_tab = k ? d_qkvA1 : d_qkvA0;
    const float* kv_tab = k ? d_kv1 : d_kv0;
    float* sum_tab = k ? d_sum1 : d_sum0;
    float* cnt_tab = k ? d_cnt1 : d_cnt0;
    __syncthreads();

    float* ebO = ebase + (size_t)(g * 2 + w) * EB_STRIDE;  // own edge buffer
    float* eb0 = ebase + (size_t)(g * 2 + 0) * EB_STRIDE;
    float* eb1 = ebase + (size_t)(g * 2 + 1) * EB_STRIDE;

    // hoisted LN params (per-lane, 2 column halves)
    float g1lo = vec[192 + lane], g1hi = vec[224 + lane];
    float be1lo = vec[256 + lane], be1hi = vec[288 + lane];
    float g2lo = vec[320 + lane], g2hi = vec[352 + lane];
    float be2lo = vec[384 + lane], be2hi = vec[416 + lane];

#define BARG() asm volatile("bar.sync %0, 64;" ::"r"(g + 1) : "memory")

    for (int e0 = blockIdx.x * 8; e0 < NE; e0 += gridDim.x * 8) {
        int eo = e0 + g * 2 + w;  // own edge
        int src = eidx[eo];
        int dst = eidx[NE + eo];

        // ---- gather own edge (warp-local) ----
        {
            const float4* gq = (const float4*)(qkv_tab + (size_t)dst * 768);
            const float4* gk = (const float4*)(kv_tab + (size_t)src * 512);
            const float4* gx = (const float4*)(x_dst + (size_t)dst * 256);
            float4* dq = (float4*)(ebO + EB_EQ);
            float4* dk = (float4*)(ebO + EB_EK);
            float4* dx = (float4*)(ebO + EB_EX);
#pragma unroll
            for (int i = 0; i < 6; i++) dq[lane + 32 * i] = gq[lane + 32 * i];
#pragma unroll
            for (int i = 0; i < 4; i++) dk[lane + 32 * i] = gk[lane + 32 * i];
#pragma unroll
            for (int i = 0; i < 2; i++) dx[lane + 32 * i] = gx[lane + 32 * i];
        }
        __syncwarp();

        // ---- attention scores + softmax own edge (lane: s=lane/8, t=lane%8) ----
        {
            int s = lane >> 3, t = lane & 7;
            const float* qb = ebO + EB_EQ + s * 192;
            const float* kb = (t < 4) ? (ebO + EB_EQ + t * 192 + 64) : (ebO + EB_EK + (t - 4) * 128);
#pragma unroll
            for (int h = 0; h < 4; h++) {
                const float4* qp = (const float4*)(qb + h * 16);
                const float4* kp = (const float4*)(kb + h * 16);
                float acc = 0.f;
#pragma unroll
                for (int j = 0; j < 4; j++) {
                    float4 a = qp[j], b = kp[j];
                    acc += a.x * b.x + a.y * b.y + a.z * b.z + a.w * b.w;
                }
                acc *= 0.25f;  // 1/sqrt(16)
                float mx = acc;
#pragma unroll
                for (int o = 4; o; o >>= 1) mx = fmaxf(mx, __shfl_xor_sync(~0u, mx, o, 8));
                float ex = __expf(acc - mx);
                float se = ex;
#pragma unroll
                for (int o = 4; o; o >>= 1) se += __shfl_xor_sync(~0u, se, o, 8);
                ebO[EB_EA + h * 32 + lane] = ex / se;
            }
        }
        __syncwarp();

        // ---- o = a @ v own edge (thread = cols lane, lane+32; v cached in regs) ----
        {
            float vlo[8], vhi[8];
#pragma unroll
            for (int t = 0; t < 4; t++) {
                vlo[t] = ebO[EB_EQ + t * 192 + 128 + lane];
                vhi[t] = ebO[EB_EQ + t * 192 + 128 + lane + 32];
                vlo[4 + t] = ebO[EB_EK + t * 128 + 64 + lane];
                vhi[4 + t] = ebO[EB_EK + t * 128 + 64 + lane + 32];
            }
            int h0 = lane >> 4;      // head of col lane (0/1)
            int h1 = h0 + 2;         // head of col lane+32 (2/3)
#pragma unroll
            for (int s = 0; s < 4; s++) {
                float4 a0 = *(const float4*)(ebO + EB_EA + h0 * 32 + s * 8);
                float4 a1 = *(const float4*)(ebO + EB_EA + h0 * 32 + s * 8 + 4);
                float4 b0 = *(const float4*)(ebO + EB_EA + h1 * 32 + s * 8);
                float4 b1 = *(const float4*)(ebO + EB_EA + h1 * 32 + s * 8 + 4);
                float olo = a0.x * vlo[0] + a0.y * vlo[1] + a0.z * vlo[2] + a0.w * vlo[3] +
                            a1.x * vlo[4] + a1.y * vlo[5] + a1.z * vlo[6] + a1.w * vlo[7];
                float ohi = b0.x * vhi[0] + b0.y * vhi[1] + b0.z * vhi[2] + b0.w * vhi[3] +
                            b1.x * vhi[4] + b1.y * vhi[5] + b1.z * vhi[6] + b1.w * vhi[7];
                ebO[EB_ES + s * 64 + lane] = olo;
                ebO[EB_ES + s * 64 + lane + 32] = ohi;
            }
        }
        BARG();  // B1: both edges' o ready

        // ---- u = xi + o @ Wo^T + bo (group GEMV) ----
        float acc[2][4];
#pragma unroll
        for (int s = 0; s < 4; s++) {
            acc[0][s] = eb0[EB_EX + s * 64 + t64] + vec[t64];
            acc[1][s] = eb1[EB_EX + s * 64 + t64] + vec[t64];
        }
        gemv64(sm, 0, t64, eb0 + EB_ES, eb1 + EB_ES, acc);
        BARG();  // B2: all ES reads complete
#pragma unroll
        for (int s = 0; s < 4; s++) {
            eb0[EB_ES + s * 64 + t64] = acc[0][s];
            eb1[EB_ES + s * 64 + t64] = acc[1][s];
        }
        BARG();  // B3: u ready

        // ---- LN1 own edge (shuffle stats) -> x1 into EX ----
#pragma unroll
        for (int s = 0; s < 4; s++) {
            float v1 = ebO[EB_ES + s * 64 + lane];
            float v2 = ebO[EB_ES + s * 64 + lane + 32];
            float sum = v1 + v2, ss = v1 * v1 + v2 * v2;
#pragma unroll
            for (int o = 16; o; o >>= 1) {
                sum += __shfl_xor_sync(~0u, sum, o);
                ss += __shfl_xor_sync(~0u, ss, o);
            }
            float mean = sum * 0.015625f;
            float rstd = rsqrtf(ss * 0.015625f - mean * mean + 1e-5f);
            ebO[EB_EX + s * 64 + lane] = (v1 - mean) * rstd * g1lo + be1lo;
            ebO[EB_EX + s * 64 + lane + 32] = (v2 - mean) * rstd * g1hi + be1hi;
        }
        BARG();  // B4: x1 ready

        // ---- FF1: z = relu(x1 @ W1^T + bf1) -> ES ----
#pragma unroll
        for (int s = 0; s < 4; s++) acc[0][s] = acc[1][s] = vec[64 + t64];
        gemv64(sm, 1, t64, eb0 + EB_EX, eb1 + EB_EX, acc);
#pragma unroll
        for (int s = 0; s < 4; s++) {
            eb0[EB_ES + s * 64 + t64] = fmaxf(acc[0][s], 0.f);
            eb1[EB_ES + s * 64 + t64] = fmaxf(acc[1][s], 0.f);
        }
        BARG();  // B5: z ready

        // ---- FF2 + residual -> u2 ----
#pragma unroll
        for (int s = 0; s < 4; s++) {
            acc[0][s] = eb0[EB_EX + s * 64 + t64] + vec[128 + t64];
            acc[1][s] = eb1[EB_EX + s * 64 + t64] + vec[128 + t64];
        }
        gemv64(sm, 2, t64, eb0 + EB_ES, eb1 + EB_ES, acc);
        BARG();  // B6: z reads complete
#pragma unroll
        for (int s = 0; s < 4; s++) {
            eb0[EB_ES + s * 64 + t64] = acc[0][s];
            eb1[EB_ES + s * 64 + t64] = acc[1][s];
        }
        BARG();  // B7: u2 ready

        // ---- LN2 own edge + atomic scatter ----
        {
            float* outp = sum_tab + (size_t)dst * 256;
#pragma unroll
            for (int s = 0; s < 4; s++) {
                float v1 = ebO[EB_ES + s * 64 + lane];
                float v2 = ebO[EB_ES + s * 64 + lane + 32];
                float sum = v1 + v2, ss = v1 * v1 + v2 * v2;
#pragma unroll
                for (int o = 16; o; o >>= 1) {
                    sum += __shfl_xor_sync(~0u, sum, o);
                    ss += __shfl_xor_sync(~0u, ss, o);
                }
                float mean = sum * 0.015625f;
                float rstd = rsqrtf(ss * 0.015625f - mean * mean + 1e-5f);
                atomicAdd(outp + s * 64 + lane, (v1 - mean) * rstd * g2lo + be2lo);
                atomicAdd(outp + s * 64 + lane + 32, (v2 - mean) * rstd * g2hi + be2hi);
            }
            if (lane == 0) atomicAdd(cnt_tab + dst, 1.0f);
        }
    }
#undef BARG
}

// ---------------- finalize: mean across types, output proj, sum over T, softmax ----------------
__global__ void finalize_kernel(const float* __restrict__ Wout, const float* __restrict__ bout,
                                float* __restrict__ out) {
    __shared__ float sW[32 * 65];
    __shared__ float sz[4][64];
    int tid = threadIdx.x;
    for (int i = tid; i < 2048; i += 128) sW[(i >> 6) * 65 + (i & 63)] = Wout[i];
    int nb = tid >> 5, lane = tid & 31;
    int n = blockIdx.x * 4 + nb;

    float c0 = d_cnt0[n], c1 = d_cnt1[n];
    float i0 = 0.5f / fmaxf(c0, 1.f);
    float i1 = 0.5f / fmaxf(c1, 1.f);
    const float* sp0 = d_sum0 + (size_t)n * 256;
    const float* sp1 = d_sum1 + (size_t)n * 256;
    for (int c = lane; c < 64; c += 32) {
        float a = 0.f, b = 0.f;
#pragma unroll
        for (int t = 0; t < 4; t++) { a += sp0[t * 64 + c]; b += sp1[t * 64 + c]; }
        sz[nb][c] = a * i0 + b * i1;
    }
    __syncthreads();

    float acc = 4.f * bout[lane];
    const float* wr = sW + lane * 65;
    const float* zz = sz[nb];
#pragma unroll 8
    for (int c = 0; c < 64; c++) acc += zz[c] * wr[c];

    float mx = acc;
    for (int o = 16; o; o >>= 1) mx = fmaxf(mx, __shfl_xor_sync(~0u, mx, o));
    float ex = __expf(acc - mx);
    float s = ex;
    for (int o = 16; o; o >>= 1) s += __shfl_xor_sync(~0u, s, o);
    out[(size_t)n * 32 + lane] = ex / s;
}

// ---------------- host ----------------
extern "C" void kernel_launch(void* const* d_in, const int* in_sizes, int n_in,
                              void* d_out, int out_size) {
    const float* x_A = (const float*)d_in[0];
    const float* x_B = (const float*)d_in[1];
    const int* e_ba = (const int*)d_in[2];
    const int* e_aa = (const int*)d_in[3];
    const float* Wb = (const float*)d_in[4];
    const float* bb = (const float*)d_in[5];
    const float* Wqkv = (const float*)d_in[6];
    const float* bqkv = (const float*)d_in[7];
    const float* Wo = (const float*)d_in[8];
    const float* bo = (const float*)d_in[9];
    const float* g1 = (const float*)d_in[10];
    const float* be1 = (const float*)d_in[11];
    const float* W1 = (const float*)d_in[12];
    const float* bf1 = (const float*)d_in[13];
    const float* W2 = (const float*)d_in[14];
    const float* bf2 = (const float*)d_in[15];
    const float* g2 = (const float*)d_in[16];
    const float* be2 = (const float*)d_in[17];
    const float* Wout = (const float*)d_in[18];
    const float* bout = (const float*)d_in[19];
    float* out = (float*)d_out;

    const int EDGE_SMEM = 28160 * 4;  // 112640 B -> 2 blocks/SM
    const int TABLE_SMEM = 10752 * 4; // 43008 B (192-col case)
    cudaFuncSetAttribute(edge_kernel, cudaFuncAttributeMaxDynamicSharedMemorySize, EDGE_SMEM);

    // zero accumulators via memset nodes
    void *p0, *p1, *pc0, *pc1;
    cudaGetSymbolAddress(&p0, d_sum0);
    cudaGetSymbolAddress(&p1, d_sum1);
    cudaGetSymbolAddress(&pc0, d_cnt0);
    cudaGetSymbolAddress(&pc1, d_cnt1);
    cudaMemsetAsync(p0, 0, (size_t)NA * 256 * 4);
    cudaMemsetAsync(p1, 0, (size_t)NA * 256 * 4);
    cudaMemsetAsync(pc0, 0, (size_t)NA * 4);
    cudaMemsetAsync(pc1, 0, (size_t)NA * 4);

    fuse_w_kernel<<<dim3(128, 2), 64>>>(Wqkv, bqkv, Wb, bb);
    table_all<<<dim3(2500, 4), 128, TABLE_SMEM>>>(x_A, x_B, Wqkv, bqkv);
    edge_kernel<<<dim3(148, 2), 256, EDGE_SMEM>>>(e_ba, e_aa, x_A, Wo, bo, g1, be1, W1, bf1, W2,
                                                  bf2, g2, be2);
    finalize_kernel<<<10000, 128>>>(Wout, bout, out);
}